// round 1
// baseline (speedup 1.0000x reference)
#include <cuda_runtime.h>
#include <cstdint>

#define NUM_HEADS 8
#define IN_BITS   64
#define N_STATE   256
#define N_OUT     64
#define K_CONN    8
#define HASH      65536
#define BATCH     128
#define T_STEPS   128
#define TOTAL_IN  320   // IN_BITS + N_STATE

// One CTA per batch element. 512 threads: thread t handles half h = t>>8 of
// neuron j = t & 255. Coefficients live in registers, packed lo/hi bytes for
// dp4a. State is a 256-byte vector in shared memory, rewritten every step.
__global__ __launch_bounds__(512, 1)
void ram_mh_kernel(const int*   __restrict__ bits,          // (B, T*64) 0/1
                   const int*   __restrict__ state_coeffs,  // (256, 320)
                   const float* __restrict__ state_mem,     // (256, 65536)
                   const int*   __restrict__ head_conn,     // (8, 64, 8)
                   const int*   __restrict__ head_coeffs,   // (8, 64, 8)
                   const float* __restrict__ head_mem,      // (8, 64, 65536)
                   float*       __restrict__ out)           // (B, 64)
{
    __shared__ uint32_t win_words[T_STEPS * 16]; // 2048 words: window bits as bytes
    __shared__ uint32_t state_words[64];         // 256 state bytes
    __shared__ uint32_t partial[N_STATE];        // half-1 partial sums

    uint8_t* state_b = reinterpret_cast<uint8_t*>(state_words);

    const int b      = blockIdx.x;
    const int t      = threadIdx.x;
    const int neuron = t & 255;
    const int h      = t >> 8;      // 0: x[0..159], 1: x[160..319]

    // ---- Preload + byte-expand all T windows into smem (once) ----
    const int4* bits4 = reinterpret_cast<const int4*>(bits + (size_t)b * (T_STEPS * IN_BITS));
    #pragma unroll
    for (int w = t; w < T_STEPS * 16; w += 512) {
        int4 v = bits4[w];
        win_words[w] = (uint32_t)(v.x & 1)
                     | ((uint32_t)(v.y & 1) << 8)
                     | ((uint32_t)(v.z & 1) << 16)
                     | ((uint32_t)(v.w & 1) << 24);
    }
    if (t < 64) state_words[t] = 0u;   // initial state = 0

    // ---- Load this thread's 160 coefficients into registers (lo/hi packed) ----
    uint32_t clo[40], chi[40];
    {
        const int4* crow = reinterpret_cast<const int4*>(
            state_coeffs + (size_t)neuron * TOTAL_IN + h * 160);
        #pragma unroll
        for (int g = 0; g < 40; g++) {
            int4 c = crow[g];
            clo[g] = (uint32_t)(c.x & 255)
                   | ((uint32_t)(c.y & 255) << 8)
                   | ((uint32_t)(c.z & 255) << 16)
                   | ((uint32_t)(c.w & 255) << 24);
            chi[g] = (uint32_t)((c.x >> 8) & 255)
                   | ((uint32_t)((c.y >> 8) & 255) << 8)
                   | ((uint32_t)((c.z >> 8) & 255) << 16)
                   | ((uint32_t)((c.w >> 8) & 255) << 24);
        }
    }
    __syncthreads();

    const float* mem_row = state_mem + ((size_t)neuron << 16);
    const uint4* st4     = reinterpret_cast<const uint4*>(state_words);

    // ---- Recurrent scan ----
    for (int step = 0; step < T_STEPS; step++) {
        uint32_t alo = 0u, ahi = 0u;
        if (h == 0) {
            // words 0..15: current window; words 16..39: state words 0..23
            const uint4* w4 = reinterpret_cast<const uint4*>(win_words + step * 16);
            #pragma unroll
            for (int q = 0; q < 4; q++) {
                uint4 xw = w4[q];
                alo = __dp4a(xw.x, clo[q*4+0], alo); ahi = __dp4a(xw.x, chi[q*4+0], ahi);
                alo = __dp4a(xw.y, clo[q*4+1], alo); ahi = __dp4a(xw.y, chi[q*4+1], ahi);
                alo = __dp4a(xw.z, clo[q*4+2], alo); ahi = __dp4a(xw.z, chi[q*4+2], ahi);
                alo = __dp4a(xw.w, clo[q*4+3], alo); ahi = __dp4a(xw.w, chi[q*4+3], ahi);
            }
            #pragma unroll
            for (int q = 0; q < 6; q++) {
                uint4 xw = st4[q];
                alo = __dp4a(xw.x, clo[16+q*4+0], alo); ahi = __dp4a(xw.x, chi[16+q*4+0], ahi);
                alo = __dp4a(xw.y, clo[16+q*4+1], alo); ahi = __dp4a(xw.y, chi[16+q*4+1], ahi);
                alo = __dp4a(xw.z, clo[16+q*4+2], alo); ahi = __dp4a(xw.z, chi[16+q*4+2], ahi);
                alo = __dp4a(xw.w, clo[16+q*4+3], alo); ahi = __dp4a(xw.w, chi[16+q*4+3], ahi);
            }
        } else {
            // words 40..79: state words 24..63
            #pragma unroll
            for (int q = 0; q < 10; q++) {
                uint4 xw = st4[6 + q];
                alo = __dp4a(xw.x, clo[q*4+0], alo); ahi = __dp4a(xw.x, chi[q*4+0], ahi);
                alo = __dp4a(xw.y, clo[q*4+1], alo); ahi = __dp4a(xw.y, chi[q*4+1], ahi);
                alo = __dp4a(xw.z, clo[q*4+2], alo); ahi = __dp4a(xw.z, chi[q*4+2], ahi);
                alo = __dp4a(xw.w, clo[q*4+3], alo); ahi = __dp4a(xw.w, chi[q*4+3], ahi);
            }
        }
        uint32_t s = alo + (ahi << 8);

        if (h) partial[neuron] = s;
        __syncthreads();   // partials visible; all state reads of this step done
        if (!h) {
            uint32_t addr = (s + partial[neuron]) & 0xFFFFu;
            float v = __ldg(mem_row + addr);
            state_b[neuron] = (v >= 0.5f) ? 1u : 0u;
        }
        __syncthreads();   // new state visible for next step
    }

    // ---- Head readout (threads 0..63) ----
    if (t < N_OUT) {
        // last window's final 3 bits = bytes 61,62,63 of window 127
        uint32_t wlast = win_words[T_STEPS * 16 - 1];  // bytes 60..63
        int hidx = (int)(((wlast >> 8) & 1u) * 4u +
                         ((wlast >> 16) & 1u) * 2u +
                         ((wlast >> 24) & 1u));        // 0..7, already < NUM_HEADS
        const int o = t;
        const int base = (hidx * N_OUT + o) * K_CONN;
        uint32_t addr = 0u;
        #pragma unroll
        for (int k = 0; k < K_CONN; k++) {
            int conn = __ldg(head_conn + base + k);
            uint32_t c = (uint32_t)__ldg(head_coeffs + base + k);
            addr += state_b[conn] ? c : 0u;
        }
        addr &= 0xFFFFu;
        out[(size_t)b * N_OUT + o] =
            __ldg(head_mem + (((size_t)(hidx * N_OUT + o)) << 16) + addr);
    }
}

extern "C" void kernel_launch(void* const* d_in, const int* in_sizes, int n_in,
                              void* d_out, int out_size)
{
    const int*   bits         = (const int*)  d_in[0];
    const int*   state_coeffs = (const int*)  d_in[1];
    const float* state_mem    = (const float*)d_in[2];
    const int*   head_conn    = (const int*)  d_in[3];
    const int*   head_coeffs  = (const int*)  d_in[4];
    const float* head_mem     = (const float*)d_in[5];
    float*       out          = (float*)      d_out;

    ram_mh_kernel<<<BATCH, 512>>>(bits, state_coeffs, state_mem,
                                  head_conn, head_coeffs, head_mem, out);
}

// round 2
// speedup vs baseline: 1.3801x; 1.3801x over previous
#include <cuda_runtime.h>
#include <cstdint>

#define NUM_HEADS 8
#define IN_BITS   64
#define N_STATE   256
#define N_OUT     64
#define K_CONN    8
#define HASH      65536
#define BATCH     128
#define T_STEPS   128
#define TOTAL_IN  320   // IN_BITS + N_STATE

// Bit-packed threshold table: bit = (state_mem[n][a] >= 0.5). 2 MB, stays in L2.
__device__ uint32_t g_state_bits[N_STATE * (HASH / 32)];

// ---------------------------------------------------------------------------
// Prologue: pack state_mem (64 MB floats) into g_state_bits (2 MB).
// Each warp handles 128 consecutive floats -> 4 packed words via ballot.
// ---------------------------------------------------------------------------
__global__ void pack_state_mem_kernel(const float* __restrict__ sm)
{
    const int tid  = blockIdx.x * blockDim.x + threadIdx.x;
    const int lane = threadIdx.x & 31;
    const int gw   = tid >> 5;                 // global warp id
    const size_t base = (size_t)gw * 128;      // 128 floats per warp
    #pragma unroll
    for (int j = 0; j < 4; j++) {
        float v = sm[base + (size_t)j * 32 + lane];
        uint32_t bits = __ballot_sync(0xFFFFFFFFu, v >= 0.5f);
        if (lane == 0) g_state_bits[gw * 4 + j] = bits;
    }
}

// ---------------------------------------------------------------------------
// Main scan. One CTA per batch element, 512 threads.
// Thread t: neuron = t>>1, half h = t&1 (adjacent lanes -> shfl combine).
//   h covers window bytes [h*32, h*32+32) and state bytes [h*128, h*128+128).
// Coefficients register-resident, packed lo/hi bytes for dp4a.
// State double-buffered in smem -> ONE barrier per step.
// Window contribution for step s+1 computed while step-s gather is in flight.
// ---------------------------------------------------------------------------
__global__ __launch_bounds__(512, 1)
void ram_scan_kernel(const int*   __restrict__ bits,          // (B, T*64)
                     const int*   __restrict__ state_coeffs,  // (256, 320)
                     const int*   __restrict__ head_conn,     // (8, 64, 8)
                     const int*   __restrict__ head_coeffs,   // (8, 64, 8)
                     const float* __restrict__ head_mem,      // (8, 64, 65536)
                     float*       __restrict__ out)           // (B, 64)
{
    __shared__ uint32_t win_words[T_STEPS * 16]; // window bits as bytes, 8 KB
    __shared__ uint32_t stbuf[2][64];            // double-buffered 256-byte state

    const int b      = blockIdx.x;
    const int t      = threadIdx.x;
    const int neuron = t >> 1;
    const int h      = t & 1;

    // ---- Expand all T windows to bytes in smem ----
    const int4* bits4 = reinterpret_cast<const int4*>(bits + (size_t)b * (T_STEPS * IN_BITS));
    for (int w = t; w < T_STEPS * 16; w += 512) {
        int4 v = bits4[w];
        win_words[w] = (uint32_t)(v.x & 1)
                     | ((uint32_t)(v.y & 1) << 8)
                     | ((uint32_t)(v.z & 1) << 16)
                     | ((uint32_t)(v.w & 1) << 24);
    }
    if (t < 64) stbuf[0][t] = 0u;   // initial state = 0

    // ---- Load coefficients into registers (lo/hi byte-packed) ----
    uint32_t wlo[8], whi[8], slo[32], shi[32];
    {
        const int4* crow = reinterpret_cast<const int4*>(state_coeffs + (size_t)neuron * TOTAL_IN);
        #pragma unroll
        for (int k = 0; k < 8; k++) {           // window words h*8 .. h*8+7
            int4 c = crow[h * 8 + k];
            wlo[k] = (uint32_t)(c.x & 255) | ((uint32_t)(c.y & 255) << 8)
                   | ((uint32_t)(c.z & 255) << 16) | ((uint32_t)(c.w & 255) << 24);
            whi[k] = (uint32_t)((c.x >> 8) & 255) | ((uint32_t)((c.y >> 8) & 255) << 8)
                   | ((uint32_t)((c.z >> 8) & 255) << 16) | ((uint32_t)((c.w >> 8) & 255) << 24);
        }
        #pragma unroll
        for (int k = 0; k < 32; k++) {          // state words 16 + h*32 + k
            int4 c = crow[16 + h * 32 + k];
            slo[k] = (uint32_t)(c.x & 255) | ((uint32_t)(c.y & 255) << 8)
                   | ((uint32_t)(c.z & 255) << 16) | ((uint32_t)(c.w & 255) << 24);
            shi[k] = (uint32_t)((c.x >> 8) & 255) | ((uint32_t)((c.y >> 8) & 255) << 8)
                   | ((uint32_t)((c.z >> 8) & 255) << 16) | ((uint32_t)((c.w >> 8) & 255) << 24);
        }
    }
    __syncthreads();   // win_words + stbuf[0] ready

    const uint4* wv = reinterpret_cast<const uint4*>(win_words); // 4 uint4 / step

    // window contribution of this thread's half for a given step
    #define WIN_ACC(STEP, OUTV)                                                 \
    {                                                                           \
        uint32_t _lo = 0u, _hi = 0u;                                            \
        _Pragma("unroll")                                                       \
        for (int q = 0; q < 2; q++) {                                           \
            uint4 xw = wv[(STEP) * 4 + h * 2 + q];                              \
            _lo = __dp4a(xw.x, wlo[q*4+0], _lo); _hi = __dp4a(xw.x, whi[q*4+0], _hi); \
            _lo = __dp4a(xw.y, wlo[q*4+1], _lo); _hi = __dp4a(xw.y, whi[q*4+1], _hi); \
            _lo = __dp4a(xw.z, wlo[q*4+2], _lo); _hi = __dp4a(xw.z, whi[q*4+2], _hi); \
            _lo = __dp4a(xw.w, wlo[q*4+3], _lo); _hi = __dp4a(xw.w, whi[q*4+3], _hi); \
        }                                                                       \
        (OUTV) = _lo + (_hi << 8);                                              \
    }

    uint32_t wacc;
    WIN_ACC(0, wacc);

    const uint32_t* prow = g_state_bits + ((size_t)neuron << 11); // 2048 words/row

    for (int step = 0; step < T_STEPS; step++) {
        const int cur = step & 1, nxt = cur ^ 1;
        const uint4* st4 = reinterpret_cast<const uint4*>(stbuf[cur]);

        // state-dependent part: 128 bytes -> 64 dp4a (two chains of 32)
        uint32_t alo = 0u, ahi = 0u;
        #pragma unroll
        for (int q = 0; q < 8; q++) {
            uint4 xw = st4[h * 8 + q];
            alo = __dp4a(xw.x, slo[q*4+0], alo); ahi = __dp4a(xw.x, shi[q*4+0], ahi);
            alo = __dp4a(xw.y, slo[q*4+1], alo); ahi = __dp4a(xw.y, shi[q*4+1], ahi);
            alo = __dp4a(xw.z, slo[q*4+2], alo); ahi = __dp4a(xw.z, shi[q*4+2], ahi);
            alo = __dp4a(xw.w, slo[q*4+3], alo); ahi = __dp4a(xw.w, shi[q*4+3], ahi);
        }
        uint32_t s = alo + (ahi << 8) + wacc;
        s += __shfl_xor_sync(0xFFFFFFFFu, s, 1);   // combine halves, no smem/barrier

        const uint32_t addr = s & 0xFFFFu;
        uint32_t wword = 0u;
        if (h == 0) wword = prow[addr >> 5];       // random gather, L2-resident (2 MB)

        // overlap next step's window contribution with the gather latency
        uint32_t wacc_next = 0u;
        if (step + 1 < T_STEPS) WIN_ACC(step + 1, wacc_next);

        if (h == 0) {
            uint8_t bit = (uint8_t)((wword >> (addr & 31u)) & 1u);
            reinterpret_cast<uint8_t*>(stbuf[nxt])[neuron] = bit;
        }
        __syncthreads();   // single barrier: new state visible, old buffer free
        wacc = wacc_next;
    }

    // ---- Head readout (threads 0..63); final state is in stbuf[0] ----
    if (t < N_OUT) {
        const uint8_t* state_b = reinterpret_cast<const uint8_t*>(stbuf[0]);
        uint32_t wlast = win_words[T_STEPS * 16 - 1];   // bytes 60..63 of last window
        int hidx = (int)(((wlast >> 8) & 1u) * 4u +
                         ((wlast >> 16) & 1u) * 2u +
                         ((wlast >> 24) & 1u));          // 0..7
        const int o = t;
        const int base = (hidx * N_OUT + o) * K_CONN;
        uint32_t addr = 0u;
        #pragma unroll
        for (int k = 0; k < K_CONN; k++) {
            int conn = __ldg(head_conn + base + k);
            uint32_t c = (uint32_t)__ldg(head_coeffs + base + k);
            addr += state_b[conn] ? c : 0u;
        }
        addr &= 0xFFFFu;
        out[(size_t)b * N_OUT + o] =
            __ldg(head_mem + (((size_t)(hidx * N_OUT + o)) << 16) + addr);
    }
    #undef WIN_ACC
}

extern "C" void kernel_launch(void* const* d_in, const int* in_sizes, int n_in,
                              void* d_out, int out_size)
{
    const int*   bits         = (const int*)  d_in[0];
    const int*   state_coeffs = (const int*)  d_in[1];
    const float* state_mem    = (const float*)d_in[2];
    const int*   head_conn    = (const int*)  d_in[3];
    const int*   head_coeffs  = (const int*)  d_in[4];
    const float* head_mem     = (const float*)d_in[5];
    float*       out          = (float*)      d_out;

    // 16M floats / 128 per warp = 131072 warps = 16384 blocks x 256 threads
    pack_state_mem_kernel<<<16384, 256>>>(state_mem);
    ram_scan_kernel<<<BATCH, 512>>>(bits, state_coeffs,
                                    head_conn, head_coeffs, head_mem, out);
}

// round 3
// speedup vs baseline: 1.4264x; 1.0336x over previous
#include <cuda_runtime.h>
#include <cstdint>

#define NUM_HEADS 8
#define IN_BITS   64
#define N_STATE   256
#define N_OUT     64
#define K_CONN    8
#define HASH      65536
#define BATCH     128
#define T_STEPS   128
#define TOTAL_IN  320   // IN_BITS + N_STATE

// Bit-packed threshold table: bit = (state_mem[n][a] >= 0.5). 2 MB, L2-resident.
__device__ uint32_t g_state_bits[N_STATE * (HASH / 32)];

// ---------------------------------------------------------------------------
// Prologue: pack state_mem (64 MB floats) into g_state_bits (2 MB). BW-bound.
// ---------------------------------------------------------------------------
__global__ void pack_state_mem_kernel(const float* __restrict__ sm)
{
    const int tid  = blockIdx.x * blockDim.x + threadIdx.x;
    const int lane = threadIdx.x & 31;
    const int gw   = tid >> 5;                 // global warp id
    const size_t base = (size_t)gw * 128;      // 128 floats per warp
    #pragma unroll
    for (int j = 0; j < 4; j++) {
        float v = sm[base + (size_t)j * 32 + lane];
        uint32_t bits = __ballot_sync(0xFFFFFFFFu, v >= 0.5f);
        if (lane == 0) g_state_bits[gw * 4 + j] = bits;
    }
}

// ---------------------------------------------------------------------------
// Main scan. One CTA per batch element, 256 threads, thread t = neuron t.
// Each thread owns the FULL 320-input dot for its neuron: coefficients
// register-resident (lo/hi byte-packed for dp4a), state bytes broadcast from
// smem, window bytes broadcast from smem. One gather + one barrier per step.
// Window contribution of step s+1 is computed while the step-s gather flies.
// ---------------------------------------------------------------------------
__global__ __launch_bounds__(256, 1)
void ram_scan_kernel(const int*   __restrict__ bits,          // (B, T*64)
                     const int*   __restrict__ state_coeffs,  // (256, 320)
                     const int*   __restrict__ head_conn,     // (8, 64, 8)
                     const int*   __restrict__ head_coeffs,   // (8, 64, 8)
                     const float* __restrict__ head_mem,      // (8, 64, 65536)
                     float*       __restrict__ out)           // (B, 64)
{
    __shared__ uint32_t win_words[T_STEPS * 16]; // window bits as bytes, 8 KB
    __shared__ uint32_t stbuf[2][64];            // double-buffered 256-byte state

    const int b = blockIdx.x;
    const int t = threadIdx.x;                   // neuron id

    // ---- Expand all T windows to bytes in smem ----
    const int4* bits4 = reinterpret_cast<const int4*>(bits + (size_t)b * (T_STEPS * IN_BITS));
    for (int w = t; w < T_STEPS * 16; w += 256) {
        int4 v = bits4[w];
        win_words[w] = (uint32_t)(v.x & 1)
                     | ((uint32_t)(v.y & 1) << 8)
                     | ((uint32_t)(v.z & 1) << 16)
                     | ((uint32_t)(v.w & 1) << 24);
    }
    if (t < 64) stbuf[0][t] = 0u;   // initial state = 0

    // ---- Load this neuron's 320 coefficients into registers ----
    uint32_t wlo[16], whi[16], clo[64], chi[64];
    {
        const int4* crow = reinterpret_cast<const int4*>(state_coeffs + (size_t)t * TOTAL_IN);
        #pragma unroll
        for (int k = 0; k < 16; k++) {          // window words 0..15
            int4 c = crow[k];
            wlo[k] = (uint32_t)(c.x & 255) | ((uint32_t)(c.y & 255) << 8)
                   | ((uint32_t)(c.z & 255) << 16) | ((uint32_t)(c.w & 255) << 24);
            whi[k] = (uint32_t)((c.x >> 8) & 255) | ((uint32_t)((c.y >> 8) & 255) << 8)
                   | ((uint32_t)((c.z >> 8) & 255) << 16) | ((uint32_t)((c.w >> 8) & 255) << 24);
        }
        #pragma unroll
        for (int k = 0; k < 64; k++) {          // state words 16..79
            int4 c = crow[16 + k];
            clo[k] = (uint32_t)(c.x & 255) | ((uint32_t)(c.y & 255) << 8)
                   | ((uint32_t)(c.z & 255) << 16) | ((uint32_t)(c.w & 255) << 24);
            chi[k] = (uint32_t)((c.x >> 8) & 255) | ((uint32_t)((c.y >> 8) & 255) << 8)
                   | ((uint32_t)((c.z >> 8) & 255) << 16) | ((uint32_t)((c.w >> 8) & 255) << 24);
        }
    }
    __syncthreads();   // win_words + stbuf[0] ready

    const uint4* wv = reinterpret_cast<const uint4*>(win_words); // 4 uint4 / step

    // full window contribution for a given step (all lanes same addr: broadcast)
    #define WIN_ACC(STEP, OUTV)                                                  \
    {                                                                            \
        uint32_t _l0 = 0u, _h0 = 0u, _l1 = 0u, _h1 = 0u;                         \
        _Pragma("unroll")                                                        \
        for (int q = 0; q < 4; q += 2) {                                         \
            uint4 x0 = wv[(STEP) * 4 + q];                                       \
            uint4 x1 = wv[(STEP) * 4 + q + 1];                                   \
            _l0 = __dp4a(x0.x, wlo[q*4+0], _l0); _h0 = __dp4a(x0.x, whi[q*4+0], _h0); \
            _l0 = __dp4a(x0.y, wlo[q*4+1], _l0); _h0 = __dp4a(x0.y, whi[q*4+1], _h0); \
            _l0 = __dp4a(x0.z, wlo[q*4+2], _l0); _h0 = __dp4a(x0.z, whi[q*4+2], _h0); \
            _l0 = __dp4a(x0.w, wlo[q*4+3], _l0); _h0 = __dp4a(x0.w, whi[q*4+3], _h0); \
            _l1 = __dp4a(x1.x, wlo[q*4+4], _l1); _h1 = __dp4a(x1.x, whi[q*4+4], _h1); \
            _l1 = __dp4a(x1.y, wlo[q*4+5], _l1); _h1 = __dp4a(x1.y, whi[q*4+5], _h1); \
            _l1 = __dp4a(x1.z, wlo[q*4+6], _l1); _h1 = __dp4a(x1.z, whi[q*4+6], _h1); \
            _l1 = __dp4a(x1.w, wlo[q*4+7], _l1); _h1 = __dp4a(x1.w, whi[q*4+7], _h1); \
        }                                                                        \
        (OUTV) = (_l0 + _l1) + ((_h0 + _h1) << 8);                               \
    }

    uint32_t wacc;
    WIN_ACC(0, wacc);

    const uint32_t* prow = g_state_bits + ((size_t)t << 11); // 2048 words/row

    #pragma unroll 2
    for (int step = 0; step < T_STEPS; step++) {
        const int cur = step & 1, nxt = cur ^ 1;
        const uint4* st4 = reinterpret_cast<const uint4*>(stbuf[cur]);

        // state-dependent dot: 256 bytes, 128 dp4a in 4 chains of 32
        uint32_t a0 = 0u, a1 = 0u, h0 = 0u, h1 = 0u;
        #pragma unroll
        for (int q = 0; q < 16; q += 2) {
            uint4 x0 = st4[q];
            uint4 x1 = st4[q + 1];
            a0 = __dp4a(x0.x, clo[q*4+0], a0); h0 = __dp4a(x0.x, chi[q*4+0], h0);
            a0 = __dp4a(x0.y, clo[q*4+1], a0); h0 = __dp4a(x0.y, chi[q*4+1], h0);
            a0 = __dp4a(x0.z, clo[q*4+2], a0); h0 = __dp4a(x0.z, chi[q*4+2], h0);
            a0 = __dp4a(x0.w, clo[q*4+3], a0); h0 = __dp4a(x0.w, chi[q*4+3], h0);
            a1 = __dp4a(x1.x, clo[q*4+4], a1); h1 = __dp4a(x1.x, chi[q*4+4], h1);
            a1 = __dp4a(x1.y, clo[q*4+5], a1); h1 = __dp4a(x1.y, chi[q*4+5], h1);
            a1 = __dp4a(x1.z, clo[q*4+6], a1); h1 = __dp4a(x1.z, chi[q*4+6], h1);
            a1 = __dp4a(x1.w, clo[q*4+7], a1); h1 = __dp4a(x1.w, chi[q*4+7], h1);
        }
        const uint32_t s    = (a0 + a1) + ((h0 + h1) << 8) + wacc;
        const uint32_t addr = s & 0xFFFFu;

        // random gather (L2-resident 2 MB table); issued before window work
        const uint32_t wword = prow[addr >> 5];

        // next step's window contribution in the gather's latency shadow
        uint32_t wacc_next;
        WIN_ACC((step + 1) & (T_STEPS - 1), wacc_next);

        reinterpret_cast<uint8_t*>(stbuf[nxt])[t] =
            (uint8_t)((wword >> (addr & 31u)) & 1u);
        __syncthreads();   // new state visible; old buffer free
        wacc = wacc_next;
    }

    // ---- Head readout (threads 0..63); final state is in stbuf[0] ----
    if (t < N_OUT) {
        const uint8_t* state_b = reinterpret_cast<const uint8_t*>(stbuf[0]);
        uint32_t wlast = win_words[T_STEPS * 16 - 1];   // bytes 60..63 of last window
        int hidx = (int)(((wlast >> 8) & 1u) * 4u +
                         ((wlast >> 16) & 1u) * 2u +
                         ((wlast >> 24) & 1u));          // 0..7
        const int o = t;
        const int base = (hidx * N_OUT + o) * K_CONN;
        uint32_t addr = 0u;
        #pragma unroll
        for (int k = 0; k < K_CONN; k++) {
            int conn = __ldg(head_conn + base + k);
            uint32_t c = (uint32_t)__ldg(head_coeffs + base + k);
            addr += state_b[conn] ? c : 0u;
        }
        addr &= 0xFFFFu;
        out[(size_t)b * N_OUT + o] =
            __ldg(head_mem + (((size_t)(hidx * N_OUT + o)) << 16) + addr);
    }
    #undef WIN_ACC
}

extern "C" void kernel_launch(void* const* d_in, const int* in_sizes, int n_in,
                              void* d_out, int out_size)
{
    const int*   bits         = (const int*)  d_in[0];
    const int*   state_coeffs = (const int*)  d_in[1];
    const float* state_mem    = (const float*)d_in[2];
    const int*   head_conn    = (const int*)  d_in[3];
    const int*   head_coeffs  = (const int*)  d_in[4];
    const float* head_mem     = (const float*)d_in[5];
    float*       out          = (float*)      d_out;

    pack_state_mem_kernel<<<16384, 256>>>(state_mem);
    ram_scan_kernel<<<BATCH, 256>>>(bits, state_coeffs,
                                    head_conn, head_coeffs, head_mem, out);
}